// round 1
// baseline (speedup 1.0000x reference)
#include <cuda_runtime.h>
#include <math.h>

#define EPS 1e-20f
#define Bn 4
#define Cn 32
#define On 32
#define Hn 256
#define Wn 256
#define HOn 128
#define WOn 128
#define HWO (HOn*WOn)      /* 16384 */
#define KK 9

// -------- device scratch (no allocations allowed) --------
__device__ float g_P[Bn*Cn*HWO];     // cgx_sp * gx_sp
__device__ float g_Q[Bn*Cn*HWO];     // cgx_sp
__device__ float g_sw[Cn*KK];        // softplus(spatial_weight)
__device__ float g_wp[Cn];           // softplus(w_prop)
__device__ float g_cwT[Cn*On];       // softplus(channel_weight), transposed [c][o]
__device__ float g_invS;             // 1/(sum(sw)+eps)
__device__ float g_invS2_4;          // 0.25/(sum(cw)+eps)

__device__ __forceinline__ float softplusf(float x) {
    return fmaxf(x, 0.0f) + log1pf(expf(-fabsf(x)));
}

// -------- kernel 0: weights prep (tiny) --------
__global__ void prep_kernel(const float* __restrict__ w_prop,
                            const float* __restrict__ spatial_weight,
                            const float* __restrict__ channel_weight) {
    __shared__ float red[1024];
    int t = threadIdx.x;  // 1024 threads

    float cwv = 0.0f;
    if (t < On * Cn) {
        int o = t / Cn, c = t % Cn;
        cwv = softplusf(channel_weight[t]);   // t = o*Cn + c
        g_cwT[c * On + o] = cwv;
    }
    float swv = 0.0f;
    if (t < Cn * KK) {
        swv = softplusf(spatial_weight[t]);
        g_sw[t] = swv;
    }
    if (t < Cn) g_wp[t] = softplusf(w_prop[t]);

    // deterministic tree reduction: sum of sw
    red[t] = swv;
    __syncthreads();
    for (int s = 512; s > 0; s >>= 1) {
        if (t < s) red[t] += red[t + s];
        __syncthreads();
    }
    if (t == 0) g_invS = 1.0f / (red[0] + EPS);
    __syncthreads();

    // sum of cw
    red[t] = cwv;
    __syncthreads();
    for (int s = 512; s > 0; s >>= 1) {
        if (t < s) red[t] += red[t + s];
        __syncthreads();
    }
    if (t == 0) g_invS2_4 = 0.25f / (red[0] + EPS);
}

// -------- kernel 1: stage1 + spatial (per (b,c), 8 output rows per block) --------
// Stage1 exact simplification (given the reference's mask-style pad_r/pad_l):
//   cgx_from_ds = s^3 * cd^2 for 0<x<W-1, else 0;  gx_from_ds term contributes 0 always.
//   U = wp*cgx*gx            (numerator of gx1 * (V+eps))
//   V = wp*cgx + cgx_from_ds (cgx1 = V/(wp+1), gx1 = U/(V+eps))
// Spatial:  nom = sum_k sw_k*sprod_k*U_k/(wp+1);  den = sum_k sw_k*sprod_k*V_k/(wp+1)
//   P = gx_sp*cgx_sp = nom*den/((den+eps)(S+eps)) ~= nom/(S+eps)   (err ~ eps/den)
//   Q = cgx_sp = den/(S+eps)
__global__ __launch_bounds__(256) void spatial_kernel(
    const float* __restrict__ s_in, const float* __restrict__ cd,
    const float* __restrict__ gx,   const float* __restrict__ cgx,
    const float* __restrict__ sprod)
{
    __shared__ float sU[17][256];
    __shared__ float sV[17][256];
    __shared__ float s_sw[KK];

    const int bc  = blockIdx.x;          // b*Cn + c
    const int c   = bc & (Cn - 1);
    const int ho0 = blockIdx.y * 8;
    const int ir0 = 2 * ho0 - 1;
    const int t   = threadIdx.x;

    const float wp = g_wp[c];
    if (t < KK) s_sw[t] = g_sw[c * KK + t];
    const float invS    = g_invS;
    const float inv_wp1 = 1.0f / (wp + 1.0f);

    const size_t plane = (size_t)bc * (Hn * Wn);

    // ---- stage U,V for 17 input rows x 256 cols (float4-coalesced) ----
    for (int idx = t; idx < 17 * 64; idx += 256) {
        const int r  = idx >> 6;
        const int g4 = idx & 63;
        const int ir = ir0 + r;
        float u[4], v[4];
        if (ir >= 0 && ir < Hn) {
            const size_t base = plane + (size_t)ir * Wn + g4 * 4;
            const float4 sx  = *(const float4*)(s_in + base);
            const float4 cdx = *(const float4*)(cd   + base);
            const float4 gxx = *(const float4*)(gx   + base);
            const float4 cgv = *(const float4*)(cgx  + base);
            const float se[4]  = {sx.x,  sx.y,  sx.z,  sx.w};
            const float cde[4] = {cdx.x, cdx.y, cdx.z, cdx.w};
            const float ge[4]  = {gxx.x, gxx.y, gxx.z, gxx.w};
            const float cge[4] = {cgv.x, cgv.y, cgv.z, cgv.w};
            #pragma unroll
            for (int e = 0; e < 4; e++) {
                const int x = g4 * 4 + e;
                const float cgds = (x == 0 || x == Wn - 1)
                                 ? 0.0f
                                 : se[e] * se[e] * se[e] * cde[e] * cde[e];
                u[e] = wp * cge[e] * ge[e];
                v[e] = wp * cge[e] + cgds;
            }
        } else {
            #pragma unroll
            for (int e = 0; e < 4; e++) { u[e] = 0.0f; v[e] = 0.0f; }
        }
        #pragma unroll
        for (int e = 0; e < 4; e++) {
            sU[r][g4 * 4 + e] = u[e];
            sV[r][g4 * 4 + e] = v[e];
        }
    }
    __syncthreads();

    // ---- spatial 3x3 stride-2 reduce (4 output pixels per thread) ----
    const int wo = t & 127;
    const int hb = t >> 7;            // 0 or 1
    #pragma unroll
    for (int it = 0; it < 4; ++it) {
        const int hloc = hb + it * 2;
        const int ho   = ho0 + hloc;
        float nom = 0.0f, den = 0.0f;
        const size_t spbase = (size_t)bc * KK * HWO + (size_t)ho * WOn + wo;
        #pragma unroll
        for (int i = 0; i < 3; i++) {
            const int r = 2 * hloc + i;
            #pragma unroll
            for (int j = 0; j < 3; j++) {
                const int x = 2 * wo - 1 + j;
                if (x >= 0 && x < Wn) {
                    const float sp = sprod[spbase + (size_t)(i * 3 + j) * HWO];
                    const float w  = s_sw[i * 3 + j] * sp;
                    nom += w * sU[r][x];
                    den += w * sV[r][x];
                }
            }
        }
        nom *= inv_wp1;
        den *= inv_wp1;
        const size_t oidx = (size_t)bc * HWO + (size_t)ho * WOn + wo;
        g_P[oidx] = nom * invS;
        g_Q[oidx] = den * invS;
    }
}

// -------- kernel 2: 1x1 channel mix (dual 32x32 matvec per pixel) --------
__global__ __launch_bounds__(256) void channel_kernel(
    const float* __restrict__ bias, float* __restrict__ out)
{
    __shared__ float scw[Cn * On];   // [c][o]
    __shared__ float sbias[On];
    const int t = threadIdx.x;
    for (int i = t; i < Cn * On; i += 256) scw[i] = g_cwT[i];
    if (t < On) sbias[t] = bias[t];
    __syncthreads();
    const float invS2_4 = g_invS2_4;

    const int gidx = blockIdx.x * 256 + t;
    const int b  = gidx >> 14;         // / HWO
    const int hw = gidx & (HWO - 1);

    float nom2[On], den2[On];
    #pragma unroll
    for (int o = 0; o < On; o++) { nom2[o] = 0.0f; den2[o] = 0.0f; }

    const size_t base = (size_t)b * Cn * HWO + hw;
    #pragma unroll 4
    for (int c = 0; c < Cn; c++) {
        const float p = g_P[base + (size_t)c * HWO];
        const float q = g_Q[base + (size_t)c * HWO];
        #pragma unroll
        for (int o = 0; o < On; o++) {
            const float w = scw[c * On + o];   // broadcast LDS
            nom2[o] += p * w;
            den2[o] += q * w;
        }
    }

    const size_t obase = (size_t)b * On * HWO + hw;
    const size_t half  = (size_t)Bn * On * HWO;
    #pragma unroll
    for (int o = 0; o < On; o++) {
        const float gxo = (__fdividef(nom2[o], den2[o] + EPS) + sbias[o]) * 2.0f;
        out[obase + (size_t)o * HWO]        = gxo;
        out[half + obase + (size_t)o * HWO] = den2[o] * invS2_4;
    }
}

extern "C" void kernel_launch(void* const* d_in, const int* in_sizes, int n_in,
                              void* d_out, int out_size) {
    // metadata order: d, cd, s, cs, gx, cgx, s_prod_roll,
    //                 w_prop, spatial_weight, channel_weight, bias
    // (d and cs are provably unused by the math — see stage1 simplification)
    const float* cd_p    = (const float*)d_in[1];
    const float* s_p     = (const float*)d_in[2];
    const float* gx_p    = (const float*)d_in[4];
    const float* cgx_p   = (const float*)d_in[5];
    const float* sprod_p = (const float*)d_in[6];
    const float* wprop_p = (const float*)d_in[7];
    const float* sw_p    = (const float*)d_in[8];
    const float* cw_p    = (const float*)d_in[9];
    const float* bias_p  = (const float*)d_in[10];

    prep_kernel<<<1, 1024>>>(wprop_p, sw_p, cw_p);

    dim3 gA(Bn * Cn, 16);            // 2048 blocks
    spatial_kernel<<<gA, 256>>>(s_p, cd_p, gx_p, cgx_p, sprod_p);

    channel_kernel<<<(Bn * HWO) / 256, 256>>>(bias_p, (float*)d_out);
}

// round 2
// speedup vs baseline: 1.0148x; 1.0148x over previous
#include <cuda_runtime.h>
#include <math.h>

#define EPS 1e-20f
#define Bn 4
#define Cn 32
#define On 32
#define Hn 256
#define Wn 256
#define HOn 128
#define WOn 128
#define HWO (HOn*WOn)      /* 16384 */
#define KK 9

// -------- device scratch (no allocations allowed) --------
__device__ float2 g_PQ[Bn*Cn*HWO];   // (cgx_sp*gx_sp, cgx_sp) interleaved

__device__ __forceinline__ float softplusf(float x) {
    return fmaxf(x, 0.0f) + log1pf(expf(-fabsf(x)));
}

// packed f32x2 FMA (sm_103a FFMA2 — only reachable via PTX)
#define FMA2(acc, a, b) \
    asm("fma.rn.f32x2 %0, %1, %2, %3;" : "=l"(acc) : "l"(a), "l"(b), "l"(acc))

// -------- kernel 1: stage1 + spatial (per (b,c), 8 output rows per block) --------
// Stage1 exact simplification (reference's pad_r/pad_l are edge-zero masks):
//   cgx_from_ds = s^3 * cd^2 for 0<x<W-1, else 0;  gx_from_ds term contributes 0.
//   U = wp*cgx*gx ;  V = wp*cgx + cgx_from_ds  (cgx1 = V/(wp+1), gx1 = U/(V+eps))
// Spatial: nom = sum_k sw_k*sprod_k*U_k/(wp+1);  den = sum_k sw_k*sprod_k*V_k/(wp+1)
//   P = nom/(S+eps) (== gx_sp*cgx_sp to ~eps) ;  Q = den/(S+eps)
__global__ __launch_bounds__(256) void spatial_kernel(
    const float* __restrict__ s_in, const float* __restrict__ cd,
    const float* __restrict__ gx,   const float* __restrict__ cgx,
    const float* __restrict__ sprod,
    const float* __restrict__ w_prop, const float* __restrict__ spatial_weight)
{
    // parity-split tile: window taps (2wo-1, 2wo, 2wo+1) -> odd[wo], even[wo], odd[wo+1]
    __shared__ float sUe[17][128];
    __shared__ float sVe[17][128];
    __shared__ float sUo[17][132];   // [0] = zero pad (x = -1)
    __shared__ float sVo[17][132];
    __shared__ float s_sw[KK];
    __shared__ float sred[256];

    const int bc  = blockIdx.x;          // b*Cn + c
    const int c   = bc & (Cn - 1);
    const int ho0 = blockIdx.y * 8;
    const int ir0 = 2 * ho0 - 1;
    const int t   = threadIdx.x;

    // ---- inlined weight prep (deterministic, identical in every block) ----
    const float wp = softplusf(__ldg(&w_prop[c]));
    {
        float v = softplusf(__ldg(&spatial_weight[t]));                 // t < 256 < 288
        if (t < 32) v += softplusf(__ldg(&spatial_weight[256 + t]));
        sred[t] = v;
        if (t < KK) s_sw[t] = softplusf(__ldg(&spatial_weight[c * KK + t]));
        if (t < 17) { sUo[t][0] = 0.0f; sVo[t][0] = 0.0f; }
    }
    __syncthreads();
    #pragma unroll
    for (int s = 128; s > 0; s >>= 1) {
        if (t < s) sred[t] += sred[t + s];
        __syncthreads();
    }
    const float scale = (1.0f / (wp + 1.0f)) * (1.0f / (sred[0] + EPS));

    const size_t plane = (size_t)bc * (Hn * Wn);

    // ---- stage U,V for 17 input rows x 256 cols (float4-coalesced) ----
    for (int idx = t; idx < 17 * 64; idx += 256) {
        const int r  = idx >> 6;
        const int g4 = idx & 63;
        const int ir = ir0 + r;
        float u[4], v[4];
        if (ir >= 0 && ir < Hn) {
            const size_t base = plane + (size_t)ir * Wn + g4 * 4;
            const float4 sx  = *(const float4*)(s_in + base);
            const float4 cdx = *(const float4*)(cd   + base);
            const float4 gxx = *(const float4*)(gx   + base);
            const float4 cgv = *(const float4*)(cgx  + base);
            const float se[4]  = {sx.x,  sx.y,  sx.z,  sx.w};
            const float cde[4] = {cdx.x, cdx.y, cdx.z, cdx.w};
            const float ge[4]  = {gxx.x, gxx.y, gxx.z, gxx.w};
            const float cge[4] = {cgv.x, cgv.y, cgv.z, cgv.w};
            #pragma unroll
            for (int e = 0; e < 4; e++) {
                const int x = g4 * 4 + e;
                const float cgds = (x == 0 || x == Wn - 1)
                                 ? 0.0f
                                 : se[e] * se[e] * se[e] * cde[e] * cde[e];
                u[e] = wp * cge[e] * ge[e];
                v[e] = wp * cge[e] + cgds;
            }
        } else {
            #pragma unroll
            for (int e = 0; e < 4; e++) { u[e] = 0.0f; v[e] = 0.0f; }
        }
        // parity-split store: even x -> [x/2], odd x -> [x/2 + 1]
        sUe[r][2 * g4]     = u[0];
        sUo[r][2 * g4 + 1] = u[1];
        sUe[r][2 * g4 + 1] = u[2];
        sUo[r][2 * g4 + 2] = u[3];
        sVe[r][2 * g4]     = v[0];
        sVo[r][2 * g4 + 1] = v[1];
        sVe[r][2 * g4 + 1] = v[2];
        sVo[r][2 * g4 + 2] = v[3];
    }
    __syncthreads();

    // ---- spatial 3x3 stride-2 reduce (4 output pixels per thread, no branches) ----
    const int wo = t & 127;
    const int hb = t >> 7;            // 0 or 1
    #pragma unroll
    for (int it = 0; it < 4; ++it) {
        const int hloc = hb + it * 2;
        const int ho   = ho0 + hloc;
        float nom = 0.0f, den = 0.0f;
        const size_t spbase = (size_t)bc * KK * HWO + (size_t)ho * WOn + wo;
        #pragma unroll
        for (int i = 0; i < 3; i++) {
            const int r = 2 * hloc + i;
            const float sp0 = sprod[spbase + (size_t)(i * 3 + 0) * HWO];
            const float sp1 = sprod[spbase + (size_t)(i * 3 + 1) * HWO];
            const float sp2 = sprod[spbase + (size_t)(i * 3 + 2) * HWO];
            const float w0 = s_sw[i * 3 + 0] * sp0;   // x = 2wo-1 (odd)
            const float w1 = s_sw[i * 3 + 1] * sp1;   // x = 2wo   (even)
            const float w2 = s_sw[i * 3 + 2] * sp2;   // x = 2wo+1 (odd)
            nom += w0 * sUo[r][wo];
            den += w0 * sVo[r][wo];
            nom += w1 * sUe[r][wo];
            den += w1 * sVe[r][wo];
            nom += w2 * sUo[r][wo + 1];
            den += w2 * sVo[r][wo + 1];
        }
        const size_t oidx = (size_t)bc * HWO + (size_t)ho * WOn + wo;
        g_PQ[oidx] = make_float2(nom * scale, den * scale);
    }
}

// -------- kernel 2: 1x1 channel mix; 2 pixels/thread, packed f32x2 FMA --------
__global__ __launch_bounds__(128) void channel_kernel(
    const float* __restrict__ channel_weight, const float* __restrict__ bias,
    float* __restrict__ out)
{
    __shared__ unsigned long long scw2[Cn * On];  // [c][o], {w,w} packed
    __shared__ float sred[128];
    __shared__ float sbias[On];
    const int t = threadIdx.x;

    // inlined weight prep
    float partial = 0.0f;
    #pragma unroll
    for (int i = t; i < Cn * On; i += 128) {
        const int o = i >> 5, c = i & 31;
        const float w = softplusf(__ldg(&channel_weight[i]));  // i = o*Cn + c
        const unsigned wu = __float_as_uint(w);
        scw2[c * On + o] = ((unsigned long long)wu << 32) | wu;
        partial += w;
    }
    if (t < On) sbias[t] = __ldg(&bias[t]);
    sred[t] = partial;
    __syncthreads();
    #pragma unroll
    for (int s = 64; s > 0; s >>= 1) {
        if (t < s) sred[t] += sred[t + s];
        __syncthreads();
    }
    const float invS2_4 = 0.25f / (sred[0] + EPS);

    // two adjacent pixels per thread
    const int pix0 = (blockIdx.x * 128 + t) * 2;
    const int b    = pix0 >> 14;         // / HWO
    const int hw   = pix0 & (HWO - 1);   // even

    unsigned long long acc0[On], acc1[On];
    #pragma unroll
    for (int o = 0; o < On; o++) { acc0[o] = 0ull; acc1[o] = 0ull; }

    const unsigned long long* PQ =
        (const unsigned long long*)g_PQ + (size_t)b * Cn * HWO + hw;
    #pragma unroll 2
    for (int c = 0; c < Cn; c++) {
        const unsigned long long pq0 = PQ[(size_t)c * HWO];
        const unsigned long long pq1 = PQ[(size_t)c * HWO + 1];
        #pragma unroll
        for (int o = 0; o < On; o++) {
            const unsigned long long ww = scw2[c * On + o];  // broadcast LDS.64
            FMA2(acc0[o], pq0, ww);
            FMA2(acc1[o], pq1, ww);
        }
    }

    const size_t obase = (size_t)b * On * HWO + hw;
    const size_t half  = (size_t)Bn * On * HWO;
    #pragma unroll
    for (int o = 0; o < On; o++) {
        const float n0 = __uint_as_float((unsigned)acc0[o]);
        const float d0 = __uint_as_float((unsigned)(acc0[o] >> 32));
        const float n1 = __uint_as_float((unsigned)acc1[o]);
        const float d1 = __uint_as_float((unsigned)(acc1[o] >> 32));
        const float g0 = (__fdividef(n0, d0 + EPS) + sbias[o]) * 2.0f;
        const float g1 = (__fdividef(n1, d1 + EPS) + sbias[o]) * 2.0f;
        *(float2*)&out[obase + (size_t)o * HWO]        = make_float2(g0, g1);
        *(float2*)&out[half + obase + (size_t)o * HWO] =
            make_float2(d0 * invS2_4, d1 * invS2_4);
    }
}

extern "C" void kernel_launch(void* const* d_in, const int* in_sizes, int n_in,
                              void* d_out, int out_size) {
    // metadata order: d, cd, s, cs, gx, cgx, s_prod_roll,
    //                 w_prop, spatial_weight, channel_weight, bias
    // (d and cs are provably unused — see stage1 simplification)
    const float* cd_p    = (const float*)d_in[1];
    const float* s_p     = (const float*)d_in[2];
    const float* gx_p    = (const float*)d_in[4];
    const float* cgx_p   = (const float*)d_in[5];
    const float* sprod_p = (const float*)d_in[6];
    const float* wprop_p = (const float*)d_in[7];
    const float* sw_p    = (const float*)d_in[8];
    const float* cw_p    = (const float*)d_in[9];
    const float* bias_p  = (const float*)d_in[10];

    dim3 gA(Bn * Cn, 16);            // 2048 blocks
    spatial_kernel<<<gA, 256>>>(s_p, cd_p, gx_p, cgx_p, sprod_p, wprop_p, sw_p);

    channel_kernel<<<(Bn * HWO) / (2 * 128), 128>>>(cw_p, bias_p, (float*)d_out);
}

// round 3
// speedup vs baseline: 1.0644x; 1.0489x over previous
#include <cuda_runtime.h>
#include <math.h>

#define EPS 1e-20f
#define Bn 4
#define Cn 32
#define On 32
#define Hn 256
#define Wn 256
#define HOn 128
#define WOn 128
#define HWO (HOn*WOn)      /* 16384 */
#define KK 9

// -------- device scratch (no allocations allowed) --------
__device__ float2 g_PQ[Bn*Cn*HWO];   // (cgx_sp*gx_sp, cgx_sp) interleaved

__device__ __forceinline__ float softplusf(float x) {
    return fmaxf(x, 0.0f) + log1pf(expf(-fabsf(x)));
}

// packed f32x2 FMA (sm_103a FFMA2 — only reachable via PTX)
#define FMA2(acc, a, b) \
    asm("fma.rn.f32x2 %0, %1, %2, %3;" : "=l"(acc) : "l"(a), "l"(b), "l"(acc))

// -------- kernel 1: stage1 + spatial (per (b,c), 8 output rows per block) --------
// Stage1 exact simplification (reference's pad_r/pad_l are edge-zero masks):
//   cgx_from_ds = s^3 * cd^2 for 0<x<W-1, else 0;  gx_from_ds term contributes 0.
//   U = wp*cgx*gx ;  V = wp*cgx + cgx_from_ds
// Spatial: nom = sum_k sw_k*sprod_k*U_k/(wp+1);  den = sum_k sw_k*sprod_k*V_k/(wp+1)
//   P = nom/(S+eps) ;  Q = den/(S+eps)
__global__ __launch_bounds__(256) void spatial_kernel(
    const float* __restrict__ s_in, const float* __restrict__ cd,
    const float* __restrict__ gx,   const float* __restrict__ cgx,
    const float* __restrict__ sprod,
    const float* __restrict__ w_prop, const float* __restrict__ spatial_weight)
{
    // parity-split tile, U,V packed: taps (2wo-1, 2wo, 2wo+1) -> odd[wo], even[wo], odd[wo+1]
    __shared__ float2 sUVe[17][128];
    __shared__ float2 sUVo[17][132];   // [0] = zero pad (x = -1)
    __shared__ float  s_sw[KK];
    __shared__ float  s_S;

    const int bc  = blockIdx.x;          // b*Cn + c
    const int c   = bc & (Cn - 1);
    const int ho0 = blockIdx.y * 8;
    const int ir0 = 2 * ho0 - 1;
    const int t   = threadIdx.x;

    const float wp = softplusf(__ldg(&w_prop[c]));

    // warp 0: sum of all 288 softplus(spatial_weight) via shuffle (no block barriers)
    if (t < 32) {
        float acc = 0.0f;
        #pragma unroll
        for (int k = 0; k < KK; k++)
            acc += softplusf(__ldg(&spatial_weight[t * KK + k]));
        #pragma unroll
        for (int off = 16; off > 0; off >>= 1)
            acc += __shfl_xor_sync(0xffffffffu, acc, off);
        if (t == 0) s_S = acc;
    }
    if (t >= 32 && t < 32 + KK)
        s_sw[t - 32] = softplusf(__ldg(&spatial_weight[c * KK + (t - 32)]));
    if (t >= 64 && t < 64 + 17)
        sUVo[t - 64][0] = make_float2(0.0f, 0.0f);

    const size_t plane = (size_t)bc * (Hn * Wn);

    // ---- stage U,V for 17 input rows x 256 cols (float4-coalesced) ----
    for (int idx = t; idx < 17 * 64; idx += 256) {
        const int r  = idx >> 6;
        const int g4 = idx & 63;
        const int ir = ir0 + r;
        float u[4], v[4];
        if (ir >= 0 && ir < Hn) {
            const size_t base = plane + (size_t)ir * Wn + g4 * 4;
            const float4 sx  = *(const float4*)(s_in + base);
            const float4 cdx = *(const float4*)(cd   + base);
            const float4 gxx = *(const float4*)(gx   + base);
            const float4 cgv = *(const float4*)(cgx  + base);
            const float se[4]  = {sx.x,  sx.y,  sx.z,  sx.w};
            const float cde[4] = {cdx.x, cdx.y, cdx.z, cdx.w};
            const float ge[4]  = {gxx.x, gxx.y, gxx.z, gxx.w};
            const float cge[4] = {cgv.x, cgv.y, cgv.z, cgv.w};
            #pragma unroll
            for (int e = 0; e < 4; e++) {
                const int x = g4 * 4 + e;
                const float cgds = (x == 0 || x == Wn - 1)
                                 ? 0.0f
                                 : se[e] * se[e] * se[e] * cde[e] * cde[e];
                u[e] = wp * cge[e] * ge[e];
                v[e] = wp * cge[e] + cgds;
            }
        } else {
            #pragma unroll
            for (int e = 0; e < 4; e++) { u[e] = 0.0f; v[e] = 0.0f; }
        }
        // parity-split store: even x -> [x/2], odd x -> [x/2 + 1]
        sUVe[r][2 * g4]     = make_float2(u[0], v[0]);
        sUVo[r][2 * g4 + 1] = make_float2(u[1], v[1]);
        sUVe[r][2 * g4 + 1] = make_float2(u[2], v[2]);
        sUVo[r][2 * g4 + 2] = make_float2(u[3], v[3]);
    }
    __syncthreads();

    const float scale = (1.0f / (wp + 1.0f)) * (1.0f / (s_S + EPS));

    // ---- spatial 3x3 stride-2 reduce (4 output pixels per thread, no branches) ----
    const int wo = t & 127;
    const int hb = t >> 7;            // 0 or 1
    #pragma unroll
    for (int it = 0; it < 4; ++it) {
        const int hloc = hb + it * 2;
        const int ho   = ho0 + hloc;
        float nom = 0.0f, den = 0.0f;
        const size_t spbase = (size_t)bc * KK * HWO + (size_t)ho * WOn + wo;
        #pragma unroll
        for (int i = 0; i < 3; i++) {
            const int r = 2 * hloc + i;
            const float sp0 = sprod[spbase + (size_t)(i * 3 + 0) * HWO];
            const float sp1 = sprod[spbase + (size_t)(i * 3 + 1) * HWO];
            const float sp2 = sprod[spbase + (size_t)(i * 3 + 2) * HWO];
            const float w0 = s_sw[i * 3 + 0] * sp0;   // x = 2wo-1 (odd)
            const float w1 = s_sw[i * 3 + 1] * sp1;   // x = 2wo   (even)
            const float w2 = s_sw[i * 3 + 2] * sp2;   // x = 2wo+1 (odd)
            const float2 a = sUVo[r][wo];
            const float2 b = sUVe[r][wo];
            const float2 d = sUVo[r][wo + 1];
            nom += w0 * a.x + w1 * b.x + w2 * d.x;
            den += w0 * a.y + w1 * b.y + w2 * d.y;
        }
        const size_t oidx = (size_t)bc * HWO + (size_t)ho * WOn + wo;
        g_PQ[oidx] = make_float2(nom * scale, den * scale);
    }
}

// -------- kernel 2: 1x1 channel mix; 1 pixel/thread, packed f32x2 FMA --------
__global__ __launch_bounds__(256) void channel_kernel(
    const float* __restrict__ channel_weight, const float* __restrict__ bias,
    float* __restrict__ out)
{
    __shared__ unsigned long long scw2[Cn * On];  // [c][o], {w,w} packed
    __shared__ float swsum[8];
    __shared__ float sbias[On];
    const int t = threadIdx.x;

    // inlined weight prep (warp shuffle reductions, 1 barrier)
    float partial = 0.0f;
    #pragma unroll
    for (int i = t; i < Cn * On; i += 256) {
        const int o = i >> 5, cc = i & 31;
        const float w = softplusf(__ldg(&channel_weight[i]));  // i = o*Cn + c
        const unsigned wu = __float_as_uint(w);
        scw2[cc * On + o] = ((unsigned long long)wu << 32) | wu;
        partial += w;
    }
    #pragma unroll
    for (int off = 16; off > 0; off >>= 1)
        partial += __shfl_xor_sync(0xffffffffu, partial, off);
    if ((t & 31) == 0) swsum[t >> 5] = partial;
    if (t < On) sbias[t] = __ldg(&bias[t]);
    __syncthreads();
    const float S2 = swsum[0] + swsum[1] + swsum[2] + swsum[3]
                   + swsum[4] + swsum[5] + swsum[6] + swsum[7];
    const float invS2_4 = 0.25f / (S2 + EPS);

    // one pixel per thread
    const int gidx = blockIdx.x * 256 + t;
    const int b    = gidx >> 14;         // / HWO
    const int hw   = gidx & (HWO - 1);

    // load all 32 (p,q) pairs up-front (MLP = 32)
    const unsigned long long* PQ =
        (const unsigned long long*)g_PQ + (size_t)b * Cn * HWO + hw;
    unsigned long long pq[Cn];
    #pragma unroll
    for (int cc = 0; cc < Cn; cc++) pq[cc] = PQ[(size_t)cc * HWO];

    const size_t obase = (size_t)b * On * HWO + hw;
    const size_t half  = (size_t)Bn * On * HWO;

    // 4 independent accumulator chains at a time; retire immediately
    #pragma unroll
    for (int og = 0; og < On; og += 4) {
        unsigned long long a0 = 0ull, a1 = 0ull, a2 = 0ull, a3 = 0ull;
        #pragma unroll
        for (int cc = 0; cc < Cn; cc++) {
            const unsigned long long p = pq[cc];
            FMA2(a0, p, scw2[cc * On + og + 0]);
            FMA2(a1, p, scw2[cc * On + og + 1]);
            FMA2(a2, p, scw2[cc * On + og + 2]);
            FMA2(a3, p, scw2[cc * On + og + 3]);
        }
        unsigned long long accs[4] = {a0, a1, a2, a3};
        #pragma unroll
        for (int k = 0; k < 4; k++) {
            const int o = og + k;
            const float n = __uint_as_float((unsigned)accs[k]);
            const float d = __uint_as_float((unsigned)(accs[k] >> 32));
            out[obase + (size_t)o * HWO]        =
                (__fdividef(n, d + EPS) + sbias[o]) * 2.0f;
            out[half + obase + (size_t)o * HWO] = d * invS2_4;
        }
    }
}

extern "C" void kernel_launch(void* const* d_in, const int* in_sizes, int n_in,
                              void* d_out, int out_size) {
    // metadata order: d, cd, s, cs, gx, cgx, s_prod_roll,
    //                 w_prop, spatial_weight, channel_weight, bias
    // (d and cs are provably unused — see stage1 simplification)
    const float* cd_p    = (const float*)d_in[1];
    const float* s_p     = (const float*)d_in[2];
    const float* gx_p    = (const float*)d_in[4];
    const float* cgx_p   = (const float*)d_in[5];
    const float* sprod_p = (const float*)d_in[6];
    const float* wprop_p = (const float*)d_in[7];
    const float* sw_p    = (const float*)d_in[8];
    const float* cw_p    = (const float*)d_in[9];
    const float* bias_p  = (const float*)d_in[10];

    dim3 gA(Bn * Cn, 16);            // 2048 blocks
    spatial_kernel<<<gA, 256>>>(s_p, cd_p, gx_p, cgx_p, sprod_p, wprop_p, sw_p);

    channel_kernel<<<(Bn * HWO) / 256, 256>>>(cw_p, bias_p, (float*)d_out);
}

// round 4
// speedup vs baseline: 1.3420x; 1.2608x over previous
#include <cuda_runtime.h>
#include <math.h>

#define EPS 1e-20f
#define Bn 4
#define Cn 32
#define On 32
#define Hn 256
#define Wn 256
#define HOn 128
#define WOn 128
#define HWO (HOn*WOn)      /* 16384 */
#define KK 9

// -------- device scratch (no allocations allowed) --------
__device__ float2 g_PQ[Bn*Cn*HWO];            // (cgx_sp*gx_sp, cgx_sp) interleaved
__device__ unsigned long long g_cw2[Cn*On];   // [c][o] softplus(cw) packed {w,w}
__device__ float g_invS2_4;                   // 0.25/(sum cw + eps)

__device__ __forceinline__ float softplusf(float x) {
    return fmaxf(x, 0.0f) + log1pf(expf(-fabsf(x)));
}

// packed f32x2 FMA (sm_103a FFMA2 — only reachable via PTX)
#define FMA2(acc, a, b) \
    asm("fma.rn.f32x2 %0, %1, %2, %3;" : "=l"(acc) : "l"(a), "l"(b), "l"(acc))

// -------- kernel 1: stage1 + spatial (per (b,c), 4 output rows per block) --------
// Stage1 exact simplification (reference's pad_r/pad_l are edge-zero masks):
//   cgx_from_ds = s^3 * cd^2 for 0<x<W-1, else 0;  gx_from_ds term contributes 0.
//   U = wp*cgx*gx ;  V = wp*cgx + cgx_from_ds
// Spatial: nom = sum_k sw_k*sprod_k*U_k/(wp+1);  den = sum_k sw_k*sprod_k*V_k/(wp+1)
//   P = nom/(S+eps) ;  Q = den/(S+eps)
__global__ __launch_bounds__(256) void spatial_kernel(
    const float* __restrict__ s_in, const float* __restrict__ cd,
    const float* __restrict__ gx,   const float* __restrict__ cgx,
    const float* __restrict__ sprod,
    const float* __restrict__ w_prop, const float* __restrict__ spatial_weight,
    const float* __restrict__ channel_weight)
{
    // parity-split tile, U,V packed: taps (2wo-1, 2wo, 2wo+1) -> odd[wo], even[wo], odd[wo+1]
    __shared__ float2 sUVe[9][128];
    __shared__ float2 sUVo[9][132];   // [0] = zero pad (x = -1)
    __shared__ float  s_sw[KK];
    __shared__ float  s_S;
    __shared__ float  s_cwsum[8];

    const int bc  = blockIdx.x;          // b*Cn + c
    const int c   = bc & (Cn - 1);
    const int ho0 = blockIdx.y * 4;
    const int ir0 = 2 * ho0 - 1;
    const int t   = threadIdx.x;

    const float wp = softplusf(__ldg(&w_prop[c]));

    // warp 0: sum of all 288 softplus(spatial_weight) via shuffle
    if (t < 32) {
        float acc = 0.0f;
        #pragma unroll
        for (int k = 0; k < KK; k++)
            acc += softplusf(__ldg(&spatial_weight[t * KK + k]));
        #pragma unroll
        for (int off = 16; off > 0; off >>= 1)
            acc += __shfl_xor_sync(0xffffffffu, acc, off);
        if (t == 0) s_S = acc;
    }
    if (t >= 32 && t < 32 + KK)
        s_sw[t - 32] = softplusf(__ldg(&spatial_weight[c * KK + (t - 32)]));
    if (t >= 64 && t < 64 + 9)
        sUVo[t - 64][0] = make_float2(0.0f, 0.0f);

    // block (0,0) additionally pre-packs channel weights for the channel kernel
    const bool cwblk = (blockIdx.x == 0) && (blockIdx.y == 0);
    if (cwblk) {
        float partial = 0.0f;
        #pragma unroll
        for (int i = t; i < Cn * On; i += 256) {
            const int o = i >> 5, cc = i & 31;
            const float w = softplusf(__ldg(&channel_weight[i]));  // i = o*Cn + cc
            const unsigned wu = __float_as_uint(w);
            g_cw2[cc * On + o] = ((unsigned long long)wu << 32) | wu;
            partial += w;
        }
        #pragma unroll
        for (int off = 16; off > 0; off >>= 1)
            partial += __shfl_xor_sync(0xffffffffu, partial, off);
        if ((t & 31) == 0) s_cwsum[t >> 5] = partial;
    }

    const size_t plane = (size_t)bc * (Hn * Wn);

    // ---- stage U,V for 9 input rows x 256 cols (float4-coalesced, streaming) ----
    for (int idx = t; idx < 9 * 64; idx += 256) {
        const int r  = idx >> 6;
        const int g4 = idx & 63;
        const int ir = ir0 + r;
        float u[4], v[4];
        if (ir >= 0 && ir < Hn) {
            const size_t base = plane + (size_t)ir * Wn + g4 * 4;
            const float4 sx  = __ldcs((const float4*)(s_in + base));
            const float4 cdx = __ldcs((const float4*)(cd   + base));
            const float4 gxx = __ldcs((const float4*)(gx   + base));
            const float4 cgv = __ldcs((const float4*)(cgx  + base));
            const float se[4]  = {sx.x,  sx.y,  sx.z,  sx.w};
            const float cde[4] = {cdx.x, cdx.y, cdx.z, cdx.w};
            const float ge[4]  = {gxx.x, gxx.y, gxx.z, gxx.w};
            const float cge[4] = {cgv.x, cgv.y, cgv.z, cgv.w};
            #pragma unroll
            for (int e = 0; e < 4; e++) {
                const int x = g4 * 4 + e;
                const float cgds = (x == 0 || x == Wn - 1)
                                 ? 0.0f
                                 : se[e] * se[e] * se[e] * cde[e] * cde[e];
                u[e] = wp * cge[e] * ge[e];
                v[e] = wp * cge[e] + cgds;
            }
        } else {
            #pragma unroll
            for (int e = 0; e < 4; e++) { u[e] = 0.0f; v[e] = 0.0f; }
        }
        // parity-split store: even x -> [x/2], odd x -> [x/2 + 1]
        sUVe[r][2 * g4]     = make_float2(u[0], v[0]);
        sUVo[r][2 * g4 + 1] = make_float2(u[1], v[1]);
        sUVe[r][2 * g4 + 1] = make_float2(u[2], v[2]);
        sUVo[r][2 * g4 + 2] = make_float2(u[3], v[3]);
    }
    __syncthreads();

    if (cwblk && t == 0) {
        g_invS2_4 = 0.25f / (s_cwsum[0] + s_cwsum[1] + s_cwsum[2] + s_cwsum[3]
                           + s_cwsum[4] + s_cwsum[5] + s_cwsum[6] + s_cwsum[7] + EPS);
    }

    const float scale = (1.0f / (wp + 1.0f)) * (1.0f / (s_S + EPS));

    // ---- spatial 3x3 stride-2 reduce (2 output pixels per thread) ----
    const int wo = t & 127;
    const int hb = t >> 7;            // 0 or 1
    #pragma unroll
    for (int it = 0; it < 2; ++it) {
        const int hloc = hb + it * 2;
        const int ho   = ho0 + hloc;
        float nom = 0.0f, den = 0.0f;
        const size_t spbase = (size_t)bc * KK * HWO + (size_t)ho * WOn + wo;
        #pragma unroll
        for (int i = 0; i < 3; i++) {
            const int r = 2 * hloc + i;
            const float sp0 = __ldcs(&sprod[spbase + (size_t)(i * 3 + 0) * HWO]);
            const float sp1 = __ldcs(&sprod[spbase + (size_t)(i * 3 + 1) * HWO]);
            const float sp2 = __ldcs(&sprod[spbase + (size_t)(i * 3 + 2) * HWO]);
            const float w0 = s_sw[i * 3 + 0] * sp0;   // x = 2wo-1 (odd)
            const float w1 = s_sw[i * 3 + 1] * sp1;   // x = 2wo   (even)
            const float w2 = s_sw[i * 3 + 2] * sp2;   // x = 2wo+1 (odd)
            const float2 a = sUVo[r][wo];
            const float2 b = sUVe[r][wo];
            const float2 d = sUVo[r][wo + 1];
            nom += w0 * a.x + w1 * b.x + w2 * d.x;
            den += w0 * a.y + w1 * b.y + w2 * d.y;
        }
        const size_t oidx = (size_t)bc * HWO + (size_t)ho * WOn + wo;
        g_PQ[oidx] = make_float2(nom * scale, den * scale);
    }
}

// -------- kernel 2: 1x1 channel mix; 2 threads/pixel (og halves), streamed pq --------
__global__ __launch_bounds__(256) void channel_kernel(
    const float* __restrict__ bias, float* __restrict__ out)
{
    __shared__ unsigned long long scw[Cn * 16];  // [cc][oo] for this block's og half
    __shared__ float sbias[16];
    const int t   = threadIdx.x;
    const int og0 = (blockIdx.x >> 8) << 4;      // 0 or 16

    #pragma unroll
    for (int i = t; i < Cn * 16; i += 256) {
        const int cc = i >> 4, oo = i & 15;
        scw[i] = g_cw2[cc * On + og0 + oo];
    }
    if (t < 16) sbias[t] = __ldg(&bias[og0 + t]);
    __syncthreads();
    const float invS2_4 = g_invS2_4;

    const int px = (blockIdx.x & 255) * 256 + t;
    const int b  = px >> 14;             // / HWO
    const int hw = px & (HWO - 1);

    const unsigned long long* PQ =
        (const unsigned long long*)g_PQ + (size_t)b * Cn * HWO + hw;

    unsigned long long acc[16];
    #pragma unroll
    for (int oo = 0; oo < 16; oo++) acc[oo] = 0ull;

    #pragma unroll
    for (int ccg = 0; ccg < Cn; ccg += 8) {
        unsigned long long pq[8];
        #pragma unroll
        for (int j = 0; j < 8; j++) pq[j] = PQ[(size_t)(ccg + j) * HWO];
        #pragma unroll
        for (int j = 0; j < 8; j++) {
            const unsigned long long p = pq[j];
            #pragma unroll
            for (int oo = 0; oo < 16; oo++)
                FMA2(acc[oo], p, scw[(ccg + j) * 16 + oo]);
        }
    }

    const size_t obase = (size_t)b * On * HWO + (size_t)og0 * HWO + hw;
    const size_t half  = (size_t)Bn * On * HWO;
    #pragma unroll
    for (int oo = 0; oo < 16; oo++) {
        const float n = __uint_as_float((unsigned)acc[oo]);
        const float d = __uint_as_float((unsigned)(acc[oo] >> 32));
        out[obase + (size_t)oo * HWO]        =
            (__fdividef(n, d + EPS) + sbias[oo]) * 2.0f;
        out[half + obase + (size_t)oo * HWO] = d * invS2_4;
    }
}

extern "C" void kernel_launch(void* const* d_in, const int* in_sizes, int n_in,
                              void* d_out, int out_size) {
    // metadata order: d, cd, s, cs, gx, cgx, s_prod_roll,
    //                 w_prop, spatial_weight, channel_weight, bias
    // (d and cs are provably unused — see stage1 simplification)
    const float* cd_p    = (const float*)d_in[1];
    const float* s_p     = (const float*)d_in[2];
    const float* gx_p    = (const float*)d_in[4];
    const float* cgx_p   = (const float*)d_in[5];
    const float* sprod_p = (const float*)d_in[6];
    const float* wprop_p = (const float*)d_in[7];
    const float* sw_p    = (const float*)d_in[8];
    const float* cw_p    = (const float*)d_in[9];
    const float* bias_p  = (const float*)d_in[10];

    dim3 gA(Bn * Cn, 32);            // 4096 blocks
    spatial_kernel<<<gA, 256>>>(s_p, cd_p, gx_p, cgx_p, sprod_p,
                                wprop_p, sw_p, cw_p);

    channel_kernel<<<512, 256>>>(bias_p, (float*)d_out);
}